// round 5
// baseline (speedup 1.0000x reference)
#include <cuda_runtime.h>

#define BB 2
#define NN 40000
#define EE 400000
#define RR 64
#define DD 64
#define LLAYERS 6
#define MASKW 1250  // (NN+31)/32

// Scratch (allocation-free rule: __device__ globals)
__device__ __align__(16) float g_x[BB * NN * DD];    // 20.5 MB
__device__ __align__(16) float g_agg[BB * NN * DD];  // 20.5 MB (invariant: all-zero at launch entry/exit)
__device__ __align__(16) float g_rel[BB * RR * DD];
__device__ __align__(16) float g_query[BB * DD];
__device__ __align__(16) float g_qpart[BB * 2 * DD];
__device__ unsigned g_mask[BB * MASKW];  // bit set => x row may be nonzero
__device__ int g_list[BB * NN];
__device__ int g_count[BB];
__device__ int g_dense;  // 1 => zero rows would produce nonzero output

// ---------------------------------------------------------------------------
// prep
// ---------------------------------------------------------------------------
__global__ void prep_kernel(const float* __restrict__ rel_reps,
                            const int* __restrict__ r_index,
                            const int* __restrict__ h_index,
                            const float* __restrict__ mlp_w,
                            const float* __restrict__ mlp_b,
                            const float* __restrict__ lin_b,
                            const float* __restrict__ ln_g,
                            const float* __restrict__ ln_b) {
    __shared__ float q_s[BB * DD];
    int t = threadIdx.x;  // 256
    for (int i = t; i < BB * MASKW; i += 256) g_mask[i] = 0u;
    if (t < BB * DD) {
        int b = t / DD, d = t % DD;
        float v = rel_reps[(b * RR + r_index[b]) * DD + d];
        g_query[t] = v;
        q_s[t] = v;
    }
    __syncthreads();
    if (t < BB) {
        int h = h_index[t];
        g_mask[t * MASKW + (h >> 5)] = 1u << (h & 31);
    }
    if (t == 0) {
        int dense = 0;
        for (int l = 0; l < LLAYERS; l++) {
            const float* lb = lin_b + l * DD;
            float mu = 0.f;
            for (int d = 0; d < DD; d++) mu += lb[d];
            mu *= (1.f / DD);
            float var = 0.f;
            for (int d = 0; d < DD; d++) {
                float dv = lb[d] - mu;
                var += dv * dv;
            }
            var *= (1.f / DD);
            float inv = rsqrtf(var + 1e-5f);
            for (int d = 0; d < DD; d++) {
                float o = (lb[d] - mu) * inv * ln_g[l * DD + d] + ln_b[l * DD + d];
                if (o > 0.f) dense = 1;
            }
        }
        g_dense = dense;
    }
    int b = t / 128, e = t % 128;
    float acc = mlp_b[e];
#pragma unroll
    for (int k = 0; k < DD; k++)
        acc = fmaf(q_s[b * DD + k], mlp_w[(DD + k) * 128 + e], acc);
    g_qpart[b * 128 + e] = acc;
}

// ---------------------------------------------------------------------------
// init x: zeros everywhere, query at h_index[b]
// ---------------------------------------------------------------------------
__global__ void init_x(const int* __restrict__ h_index) {
    int gid = blockIdx.x * 256 + threadIdx.x;
    const int per_b = NN * DD / 4;
    if (gid >= BB * per_b) return;
    int b = gid / per_b;
    int r = gid - b * per_b;
    int n = r >> 4;
    int d4 = r & 15;
    float4 v = make_float4(0.f, 0.f, 0.f, 0.f);
    if (n == __ldg(&h_index[b]))
        v = *(const float4*)&g_query[b * DD + d4 * 4];
    ((float4*)g_x)[gid] = v;
}

// ---------------------------------------------------------------------------
// per-layer relation projection + count reset + boundary row agg[b,h]=query
// ---------------------------------------------------------------------------
__global__ void relproj_kernel(const float* __restrict__ rel_reps,
                               const float* __restrict__ pw1,
                               const float* __restrict__ pb1,
                               const float* __restrict__ pw2,
                               const float* __restrict__ pb2,
                               const int* __restrict__ h_index, int l) {
    int br = blockIdx.x;
    int b = br >> 6;
    int e = threadIdx.x;  // 64
    __shared__ float in_s[DD];
    __shared__ float hid_s[DD];
    in_s[e] = rel_reps[br * DD + e];
    __syncthreads();
    const float* W1 = pw1 + l * DD * DD;
    float acc = pb1[l * DD + e];
#pragma unroll 16
    for (int k = 0; k < DD; k++) acc = fmaf(in_s[k], W1[k * DD + e], acc);
    hid_s[e] = fmaxf(acc, 0.f);
    __syncthreads();
    const float* W2 = pw2 + l * DD * DD;
    float acc2 = pb2[l * DD + e];
#pragma unroll 16
    for (int k = 0; k < DD; k++) acc2 = fmaf(hid_s[k], W2[k * DD + e], acc2);
    g_rel[br * DD + e] = acc2;

    if ((br & 63) == 0) {
        if (e == 0) g_count[b] = 0;
        int h = __ldg(&h_index[b]);
        g_agg[(b * NN + h) * DD + e] = g_query[b * DD + e];
    }
}

// ---------------------------------------------------------------------------
// message: 4 edges/thread scan; active edges batch-load x in 2x8 float4.
// launch_bounds caps regs so the latency-bound scan keeps >=32 warps/SM.
// ---------------------------------------------------------------------------
__global__ void __launch_bounds__(256, 4)
message_kernel(const int* __restrict__ edge_index,
               const int* __restrict__ edge_type) {
    int gid = blockIdx.x * 256 + threadIdx.x;
    const int per_b = EE / 4;  // 100000
    if (gid >= BB * per_b) return;
    int b = (gid >= per_b) ? 1 : 0;
    int e4 = gid - b * per_b;
    const int4 s4 = __ldg((const int4*)edge_index + e4);
    int srcs[4] = {s4.x, s4.y, s4.z, s4.w};
    const unsigned* mask = g_mask + b * MASKW;
#pragma unroll
    for (int j = 0; j < 4; j++) {
        int src = srcs[j];
        if (!((mask[src >> 5] >> (src & 31)) & 1u)) continue;
        int e = e4 * 4 + j;
        int dst = __ldg(&edge_index[EE + e]);
        int ty = __ldg(&edge_type[e]);
        if (!((mask[dst >> 5] >> (dst & 31)) & 1u))
            atomicOr(&g_mask[b * MASKW + (dst >> 5)], 1u << (dst & 31));
        const float4* xr = (const float4*)(g_x + (b * NN + src) * DD);
        const float4* rr = (const float4*)(g_rel + (b * RR + ty) * DD);
        float* ar = g_agg + (b * NN + dst) * DD;
#pragma unroll
        for (int h = 0; h < 2; h++) {
            float4 xv[8];
#pragma unroll
            for (int c = 0; c < 8; c++) xv[c] = xr[h * 8 + c];
#pragma unroll
            for (int c = 0; c < 8; c++) {
                float4 x = xv[c];
                if (x.x == 0.f && x.y == 0.f && x.z == 0.f && x.w == 0.f)
                    continue;
                float4 rv = __ldg(&rr[h * 8 + c]);
                asm volatile("red.global.add.v4.f32 [%0], {%1,%2,%3,%4};" ::"l"(
                                 ar + (h * 8 + c) * 4),
                             "f"(x.x * rv.x), "f"(x.y * rv.y), "f"(x.z * rv.z),
                             "f"(x.w * rv.w)
                             : "memory");
            }
        }
    }
}

// ---------------------------------------------------------------------------
// compact: mask -> list, warp-aggregated, order-preserving within warp.
// ---------------------------------------------------------------------------
__global__ void compact_kernel() {
    int gid = blockIdx.x * 256 + threadIdx.x;
    if (gid >= BB * NN) return;
    int b = gid / NN;
    int n = gid - b * NN;
    bool act;
    if (g_dense) {
        act = true;
        if ((n & 31) == 0) g_mask[b * MASKW + (n >> 5)] = 0xffffffffu;
    } else {
        act = (g_mask[b * MASKW + (n >> 5)] >> (n & 31)) & 1u;
    }
    unsigned bal = __ballot_sync(0xffffffffu, act);
    if (!bal) return;
    int lane = threadIdx.x & 31;
    int pos = 0;
    if (lane == 0) pos = atomicAdd(&g_count[b], __popc(bal));
    pos = __shfl_sync(0xffffffffu, pos, 0);
    if (act)
        g_list[b * NN + pos + __popc(bal & ((1u << lane) - 1u))] = n;
}

// ---------------------------------------------------------------------------
// fused linear: x = relu(LN(cat(x,agg)@W + b)) + x for active rows; agg->0.
// Block: 128 list rows x 64 dims; 128 threads, 8x8 register tile.
// ---------------------------------------------------------------------------
__global__ void __launch_bounds__(128)
linear_kernel(const float* __restrict__ lin_w,
              const float* __restrict__ lin_b,
              const float* __restrict__ ln_g,
              const float* __restrict__ ln_b, int l) {
    extern __shared__ float smem[];
    float* W_s = smem;               // [128][64]  = 32KB
    float* cat_s = smem + 128 * 64;  // [128][128] = 64KB (k-major)
    __shared__ int idx_s[128];
    int b = blockIdx.y;
    int base = blockIdx.x * 128;
    int t = threadIdx.x;  // 128
    int cnt = g_count[b];
    if (base >= cnt) return;

    idx_s[t] = (base + t < cnt) ? g_list[b * NN + base + t] : -1;

    // load weights (8192 floats = 2048 float4, 16 per thread)
    const float4* Wg = (const float4*)(lin_w + l * 128 * 64);
    float4* Ws4 = (float4*)W_s;
#pragma unroll
    for (int i = 0; i < 16; i++) Ws4[t + i * 128] = Wg[t + i * 128];

    // gather this thread's row into cat_s column t (transposed)
    int idx = idx_s[t];
    if (idx >= 0) {
        const float4* xb = (const float4*)(g_x + (b * NN + idx) * DD);
        const float4* ab = (const float4*)(g_agg + (b * NN + idx) * DD);
#pragma unroll
        for (int c = 0; c < 16; c++) {
            float4 v = xb[c];
            cat_s[(c * 4 + 0) * 128 + t] = v.x;
            cat_s[(c * 4 + 1) * 128 + t] = v.y;
            cat_s[(c * 4 + 2) * 128 + t] = v.z;
            cat_s[(c * 4 + 3) * 128 + t] = v.w;
            float4 a = ab[c];
            cat_s[(64 + c * 4 + 0) * 128 + t] = a.x;
            cat_s[(64 + c * 4 + 1) * 128 + t] = a.y;
            cat_s[(64 + c * 4 + 2) * 128 + t] = a.z;
            cat_s[(64 + c * 4 + 3) * 128 + t] = a.w;
        }
    } else {
#pragma unroll
        for (int c = 0; c < 128; c++) cat_s[c * 128 + t] = 0.f;
    }
    __syncthreads();

    int tn = t >> 3;  // 16 row groups (8 rows)
    int td = t & 7;   // 8 dim groups (8 dims)
    float acc[8][8];
    {
        float4 b0 = *(const float4*)&lin_b[l * 64 + td * 8];
        float4 b1 = *(const float4*)&lin_b[l * 64 + td * 8 + 4];
        float bb[8] = {b0.x, b0.y, b0.z, b0.w, b1.x, b1.y, b1.z, b1.w};
#pragma unroll
        for (int i = 0; i < 8; i++)
#pragma unroll
            for (int j = 0; j < 8; j++) acc[i][j] = bb[j];
    }

#pragma unroll 2
    for (int k = 0; k < 128; ++k) {
        const float4 a0 = *(const float4*)(cat_s + k * 128 + tn * 8);
        const float4 a1 = *(const float4*)(cat_s + k * 128 + tn * 8 + 4);
        const float4 w0 = *(const float4*)(W_s + k * 64 + td * 8);
        const float4 w1 = *(const float4*)(W_s + k * 64 + td * 8 + 4);
        float aa[8] = {a0.x, a0.y, a0.z, a0.w, a1.x, a1.y, a1.z, a1.w};
        float ww[8] = {w0.x, w0.y, w0.z, w0.w, w1.x, w1.y, w1.z, w1.w};
#pragma unroll
        for (int i = 0; i < 8; i++)
#pragma unroll
            for (int j = 0; j < 8; j++)
                acc[i][j] = fmaf(aa[i], ww[j], acc[i][j]);
    }

    // fused LayerNorm (+relu+shortcut); dims spread over 8 td threads
    float lng[8], lnb[8];
    {
        float4 g0 = *(const float4*)&ln_g[l * 64 + td * 8];
        float4 g1 = *(const float4*)&ln_g[l * 64 + td * 8 + 4];
        float4 c0 = *(const float4*)&ln_b[l * 64 + td * 8];
        float4 c1 = *(const float4*)&ln_b[l * 64 + td * 8 + 4];
        lng[0] = g0.x; lng[1] = g0.y; lng[2] = g0.z; lng[3] = g0.w;
        lng[4] = g1.x; lng[5] = g1.y; lng[6] = g1.z; lng[7] = g1.w;
        lnb[0] = c0.x; lnb[1] = c0.y; lnb[2] = c0.z; lnb[3] = c0.w;
        lnb[4] = c1.x; lnb[5] = c1.y; lnb[6] = c1.z; lnb[7] = c1.w;
    }
#pragma unroll
    for (int i = 0; i < 8; i++) {
        float s = 0.f, s2 = 0.f;
#pragma unroll
        for (int j = 0; j < 8; j++) {
            s += acc[i][j];
            s2 += acc[i][j] * acc[i][j];
        }
#pragma unroll
        for (int m = 1; m < 8; m <<= 1) {
            s += __shfl_xor_sync(0xffffffffu, s, m);
            s2 += __shfl_xor_sync(0xffffffffu, s2, m);
        }
        float mu = s * (1.f / 64.f);
        float var = s2 * (1.f / 64.f) - mu * mu;
        float inv = rsqrtf(var + 1e-5f);
        int row = idx_s[tn * 8 + i];
        if (row >= 0) {
            float* xr = g_x + (b * NN + row) * DD + td * 8;
            float4 x0 = *(const float4*)xr;
            float4 x1 = *(const float4*)(xr + 4);
            float xo[8] = {x0.x, x0.y, x0.z, x0.w, x1.x, x1.y, x1.z, x1.w};
            float o[8];
#pragma unroll
            for (int j = 0; j < 8; j++)
                o[j] = fmaxf((acc[i][j] - mu) * inv * lng[j] + lnb[j], 0.f) +
                       xo[j];
            *(float4*)xr = make_float4(o[0], o[1], o[2], o[3]);
            *(float4*)(xr + 4) = make_float4(o[4], o[5], o[6], o[7]);
            float* agr = g_agg + (b * NN + row) * DD + td * 8;
            *(float4*)agr = make_float4(0.f, 0.f, 0.f, 0.f);
            *(float4*)(agr + 4) = make_float4(0.f, 0.f, 0.f, 0.f);
        }
    }
}

// ---------------------------------------------------------------------------
// final: out = relu([x ; query] @ mlp_w + mlp_b); query part precomputed.
// Block: 128 nodes x 128 dims, K=64; 256 threads, 8x8 tile.
// NN % 128 != 0: clamp loads, guard stores.
// ---------------------------------------------------------------------------
__global__ void __launch_bounds__(256)
final_kernel(const float* __restrict__ mlp_w, float* __restrict__ out) {
    extern __shared__ float smem[];
    float* W_s = smem;             // [64][128] = 32KB (k-major)
    float* x_s = smem + 64 * 128;  // [64][128] = 32KB (k-major, node minor)
    int b = blockIdx.y;
    int n0 = blockIdx.x * 128;
    int t = threadIdx.x;  // 256

    const float4* Wg = (const float4*)mlp_w;  // first 64 rows = 2048 float4
    float4* Ws4 = (float4*)W_s;
#pragma unroll
    for (int i = 0; i < 8; i++) Ws4[t + i * 256] = Wg[t + i * 256];

    // load 128 node rows (K=64) transposed: 2 threads per row (clamped)
    {
        int row = t & 127;
        int half = t >> 7;  // 0/1
        int rowg = n0 + row;
        if (rowg >= NN) rowg = NN - 1;  // clamp: valid memory, never stored
        const float4* xb =
            (const float4*)(g_x + (b * NN + rowg) * DD) + half * 8;
#pragma unroll
        for (int c = 0; c < 8; c++) {
            float4 v = xb[c];
            int k0 = half * 32 + c * 4;
            x_s[(k0 + 0) * 128 + row] = v.x;
            x_s[(k0 + 1) * 128 + row] = v.y;
            x_s[(k0 + 2) * 128 + row] = v.z;
            x_s[(k0 + 3) * 128 + row] = v.w;
        }
    }
    __syncthreads();

    int tn = t >> 4;  // 16 node groups (8 nodes)
    int td = t & 15;  // 16 dim groups (8 dims)
    float acc[8][8];
#pragma unroll
    for (int i = 0; i < 8; i++)
#pragma unroll
        for (int j = 0; j < 8; j++) acc[i][j] = 0.f;

#pragma unroll 2
    for (int k = 0; k < 64; ++k) {
        const float4 a0 = *(const float4*)(x_s + k * 128 + tn * 8);
        const float4 a1 = *(const float4*)(x_s + k * 128 + tn * 8 + 4);
        const float4 w0 = *(const float4*)(W_s + k * 128 + td * 8);
        const float4 w1 = *(const float4*)(W_s + k * 128 + td * 8 + 4);
        float aa[8] = {a0.x, a0.y, a0.z, a0.w, a1.x, a1.y, a1.z, a1.w};
        float ww[8] = {w0.x, w0.y, w0.z, w0.w, w1.x, w1.y, w1.z, w1.w};
#pragma unroll
        for (int i = 0; i < 8; i++)
#pragma unroll
            for (int j = 0; j < 8; j++)
                acc[i][j] = fmaf(aa[i], ww[j], acc[i][j]);
    }

    float qp[8];
    {
        const float4 q0 = *(const float4*)&g_qpart[b * 128 + td * 8];
        const float4 q1 = *(const float4*)&g_qpart[b * 128 + td * 8 + 4];
        qp[0] = q0.x; qp[1] = q0.y; qp[2] = q0.z; qp[3] = q0.w;
        qp[4] = q1.x; qp[5] = q1.y; qp[6] = q1.z; qp[7] = q1.w;
    }

#pragma unroll
    for (int i = 0; i < 8; i++) {
        int n = n0 + tn * 8 + i;
        if (n >= NN) continue;  // guard: NN % 128 != 0
        float* op = out + ((long)(b * NN + n)) * 128 + td * 8;
        float4 o0, o1;
        o0.x = fmaxf(acc[i][0] + qp[0], 0.f);
        o0.y = fmaxf(acc[i][1] + qp[1], 0.f);
        o0.z = fmaxf(acc[i][2] + qp[2], 0.f);
        o0.w = fmaxf(acc[i][3] + qp[3], 0.f);
        o1.x = fmaxf(acc[i][4] + qp[4], 0.f);
        o1.y = fmaxf(acc[i][5] + qp[5], 0.f);
        o1.z = fmaxf(acc[i][6] + qp[6], 0.f);
        o1.w = fmaxf(acc[i][7] + qp[7], 0.f);
        *(float4*)op = o0;
        *(float4*)(op + 4) = o1;
    }
}

// ---------------------------------------------------------------------------
extern "C" void kernel_launch(void* const* d_in, const int* in_sizes, int n_in,
                              void* d_out, int out_size) {
    const float* rel_reps = (const float*)d_in[0];
    const int* h_index = (const int*)d_in[1];
    const int* r_index = (const int*)d_in[2];
    const int* edge_index = (const int*)d_in[3];
    const int* edge_type = (const int*)d_in[4];
    const float* pw1 = (const float*)d_in[5];
    const float* pb1 = (const float*)d_in[6];
    const float* pw2 = (const float*)d_in[7];
    const float* pb2 = (const float*)d_in[8];
    const float* lin_w = (const float*)d_in[9];
    const float* lin_b = (const float*)d_in[10];
    const float* ln_g = (const float*)d_in[11];
    const float* ln_b = (const float*)d_in[12];
    const float* mlp_w = (const float*)d_in[13];
    const float* mlp_b = (const float*)d_in[14];
    float* out = (float*)d_out;

    cudaFuncSetAttribute(linear_kernel,
                         cudaFuncAttributeMaxDynamicSharedMemorySize, 98304);
    cudaFuncSetAttribute(final_kernel,
                         cudaFuncAttributeMaxDynamicSharedMemorySize, 65536);

    prep_kernel<<<1, 256>>>(rel_reps, r_index, h_index, mlp_w, mlp_b, lin_b,
                            ln_g, ln_b);
    init_x<<<(BB * NN * DD / 4 + 255) / 256, 256>>>(h_index);
    for (int l = 0; l < LLAYERS; l++) {
        relproj_kernel<<<BB * RR, 64>>>(rel_reps, pw1, pb1, pw2, pb2, h_index,
                                        l);
        message_kernel<<<(BB * EE / 4 + 255) / 256, 256>>>(edge_index,
                                                           edge_type);
        compact_kernel<<<(BB * NN + 255) / 256, 256>>>();
        linear_kernel<<<dim3((NN + 127) / 128, BB), 128, 98304>>>(
            lin_w, lin_b, ln_g, ln_b, l);
    }
    final_kernel<<<dim3((NN + 127) / 128, BB), 256, 65536>>>(mlp_w, out);
}